// round 9
// baseline (speedup 1.0000x reference)
#include <cuda_runtime.h>
#include <cstdint>

typedef unsigned long long ull;

// ---------------------------------------------------------------------------
// Packed f32x2 helpers (Blackwell sm_103a): FFMA2 only reachable via PTX.
// ---------------------------------------------------------------------------
static __device__ __forceinline__ ull ffma2(ull a, ull b, ull c) {
    ull d;
    asm("fma.rn.f32x2 %0, %1, %2, %3;" : "=l"(d) : "l"(a), "l"(b), "l"(c));
    return d;
}
static __device__ __forceinline__ ull pack2(float x) {
    ull r;
    asm("mov.b64 %0, {%1, %2};" : "=l"(r) : "f"(x), "f"(x));
    return r;
}
static __device__ __forceinline__ void unpack2(ull v, float& lo, float& hi) {
    asm("mov.b64 {%0, %1}, %2;" : "=f"(lo), "=f"(hi) : "l"(v));
}

// ---------------------------------------------------------------------------
// cp.async helpers
// ---------------------------------------------------------------------------
static __device__ __forceinline__ void cp16(uint32_t dst, const void* src) {
    asm volatile("cp.async.cg.shared.global [%0], [%1], 16;\n" :: "r"(dst), "l"(src));
}
static __device__ __forceinline__ void cp_commit() {
    asm volatile("cp.async.commit_group;\n" ::);
}
template<int W>
static __device__ __forceinline__ void cp_wait() {
    asm volatile("cp.async.wait_group %0;\n" :: "n"(W));
}

// ---------------------------------------------------------------------------
// Problem constants
// ---------------------------------------------------------------------------
#define BATCH   131072
#define SEQ     199
#define DIN     200
#define TB      128         // batch rows per block
#define NTHR    512
#define LDA     132         // activation smem stride (mult of 4 -> LDS.128 A)
#define KT      16          // k-rows per W tile
#define WBUF    4096        // floats per W buffer (16 x 256 max tile)

// Shared memory layout (float offsets)
#define OFF_ACT   0                        // 256*132 = 33792
#define OFF_W     33792                    // 2*4096  =  8192
#define OFF_H     41984                    // 64*132  =  8448
#define OFF_ADV   50432                    // 32*132  =  4224
#define OFF_V     54656                    // 128
#define OFF_RED   54784                    // 1024
#define OFF_MU    55808                    // 128
#define OFF_RS    55936                    // 128
#define OFF_ET    56064                    // 128 (int)
#define SMEM_FLOATS 56192
#define SMEM_BYTES  (SMEM_FLOATS * 4)      // 224768

// ---------------------------------------------------------------------------
// Stage a W tile (nfloat4 float4's) into smem via cp.async (all threads).
// ---------------------------------------------------------------------------
static __device__ __forceinline__ void stage_tile(float* dst, const float* src,
                                                  int nfloat4, int tid)
{
    uint32_t d = (uint32_t)__cvta_generic_to_shared(dst);
    const float4* s = (const float4*)src;
    for (int i = tid; i < nfloat4; i += NTHR)
        cp16(d + i * 16, s + i);
}

// ---------------------------------------------------------------------------
// GEMM inner body: R rows (splat-packed A) x 4 col-pairs per thread.
// Thread cols: pairs {2cx + (N/4)j, +1}, j=0..3 -> W via LDS.64, lanes span
// 128B per 16-lane group -> conflict-free. A: R rows broadcast per warp.
// Per-warp wavefronts/k: A=R + W=8  (min at R=8 with N=256).
// ---------------------------------------------------------------------------
#define GEMM_BODY(i)                                                         \
  {                                                                          \
    ull pa[R];                                                               \
    if constexpr (R == 8) {                                                  \
        float4 v0 = *(const float4*)(ip + (i) * LDA);                        \
        float4 v1 = *(const float4*)(ip + (i) * LDA + 4);                    \
        pa[0] = pack2(v0.x); pa[1] = pack2(v0.y);                            \
        pa[2] = pack2(v0.z); pa[3] = pack2(v0.w);                            \
        pa[4] = pack2(v1.x); pa[5] = pack2(v1.y);                            \
        pa[6] = pack2(v1.z); pa[7] = pack2(v1.w);                            \
    } else if constexpr (R == 4) {                                           \
        float4 v0 = *(const float4*)(ip + (i) * LDA);                        \
        pa[0] = pack2(v0.x); pa[1] = pack2(v0.y);                            \
        pa[2] = pack2(v0.z); pa[3] = pack2(v0.w);                            \
    } else if constexpr (R == 2) {                                           \
        float2 v0 = *(const float2*)(ip + (i) * LDA);                        \
        pa[0] = pack2(v0.x); pa[1] = pack2(v0.y);                            \
    } else {                                                                 \
        pa[0] = pack2(ip[(i) * LDA]);                                        \
    }                                                                        \
    const ull* w64 = (const ull*)(wS + (i) * N);                             \
    _Pragma("unroll")                                                        \
    for (int j = 0; j < 4; ++j) {                                            \
      ull w = w64[cx + (N / 8) * j];                                         \
      _Pragma("unroll")                                                      \
      for (int r = 0; r < R; ++r)                                            \
        acc[r][j] = ffma2(pa[r], w, acc[r][j]);                              \
    }                                                                        \
  }

// ---------------------------------------------------------------------------
// C[TB x N] = A[TB x K] * W[K x N] + b. Register-accumulated (in-place safe).
// Double-buffered cp.async W pipeline, distance-1 prefetch; last iteration
// prefetches the NEXT gemm's first tile (16 x nextN). gt = global tile
// counter (buffer parity), advanced by ntiles.
// If PRED, only rows with etS[row]==esel commit.
// ---------------------------------------------------------------------------
template<int N, bool PRED>
static __device__ __forceinline__ void gemm_bias(
    const float* __restrict__ Wg, const float* __restrict__ bg, int K,
    const float* inS, float* wbase, float* outS,
    const float* nextW, int nextN,
    int& gt, int tid, const int* etS, int esel)
{
    constexpr int R   = N / 32;                                  // rows/thread
    constexpr int CXM = N / 8 - 1;                               // cx mask
    constexpr int RSH = (N == 256) ? 5 : (N == 128) ? 4 : (N == 64) ? 3 : 2;
    const int cx = tid & CXM;
    const int ry = tid >> RSH;

    ull acc[R][4];
    #pragma unroll
    for (int r = 0; r < R; ++r)
        #pragma unroll
        for (int j = 0; j < 4; ++j) acc[r][j] = 0ull;

    int ntiles = (K + KT - 1) / KT;
    for (int t = 0; t < ntiles; ++t) {
        cp_wait<0>();          // tile t resident
        __syncthreads();       // ...visible to all; compute t-1 fully done
        int g = t + 1;         // issue tile t+1 (own layer or next layer)
        float* dstb = wbase + ((gt + g) & 1) * WBUF;
        if (g < ntiles) {
            int rows = min(KT, K - g * KT);
            stage_tile(dstb, Wg + (size_t)g * KT * N, (rows * N) >> 2, tid);
            cp_commit();
        } else if (nextW) {
            stage_tile(dstb, nextW, (KT * nextN) >> 2, tid);
            cp_commit();
        }

        int ks = min(KT, K - t * KT);
        const float* wS = wbase + ((gt + t) & 1) * WBUF;
        const float* ip = inS + t * KT * LDA + R * ry;
        if (ks == KT) {
            #pragma unroll
            for (int i = 0; i < KT; ++i) GEMM_BODY(i)
        } else {
            for (int i = 0; i < ks; ++i) GEMM_BODY(i)
        }
    }
    gt += ntiles;

    __syncthreads();   // all reads of inS done -> safe to overwrite (in-place)
    #pragma unroll
    for (int r = 0; r < R; ++r) {
        int row = R * ry + r;
        if (!PRED || etS[row] == esel) {
            #pragma unroll
            for (int j = 0; j < 4; ++j) {
                int c0 = 2 * cx + (N / 4) * j;
                float lo, hi; unpack2(acc[r][j], lo, hi);
                outS[(c0 + 0) * LDA + row] = lo + bg[c0 + 0];
                outS[(c0 + 1) * LDA + row] = hi + bg[c0 + 1];
            }
        }
    }
    __syncthreads();
}

// ---------------------------------------------------------------------------
// In-place LayerNorm(+affine)+ReLU over feature dim N for TB=128 rows.
// 4 partial threads per row.
// ---------------------------------------------------------------------------
static __device__ __forceinline__ void ln_relu(
    float* S, int N, const float* __restrict__ g, const float* __restrict__ be,
    int tid, float* redS, float* muS, float* rsS)
{
    int row = tid & 127;
    int p   = tid >> 7;
    int seg = N >> 2;
    float s = 0.f, sq = 0.f;
    for (int i = 0; i < seg; ++i) {
        float v = S[(p * seg + i) * LDA + row];
        s += v; sq += v * v;
    }
    redS[p * 128 + row]       = s;
    redS[512 + p * 128 + row] = sq;
    __syncthreads();
    if (tid < 128) {
        float ts = 0.f, tq = 0.f;
        #pragma unroll
        for (int pp = 0; pp < 4; ++pp) {
            ts += redS[pp * 128 + tid];
            tq += redS[512 + pp * 128 + tid];
        }
        float mu  = ts / (float)N;
        float var = tq / (float)N - mu * mu;
        muS[tid] = mu;
        rsS[tid] = rsqrtf(var + 1e-5f);
    }
    __syncthreads();
    float mu = muS[row], rs = rsS[row];
    for (int i = 0; i < seg; ++i) {
        int col = p * seg + i;
        float v = S[col * LDA + row];
        v = (v - mu) * rs * g[col] + be[col];
        S[col * LDA + row] = fmaxf(v, 0.f);
    }
    __syncthreads();
}

// ---------------------------------------------------------------------------
// Fused dueling-DQN forward. One block = 128 batch rows, all layers fused.
// ---------------------------------------------------------------------------
__global__ void __launch_bounds__(NTHR, 1)
dqn_kernel(const float* __restrict__ state, const float* __restrict__ time_delta,
           const float* __restrict__ W1,  const float* __restrict__ b1,
           const float* __restrict__ g1,  const float* __restrict__ be1,
           const float* __restrict__ W2,  const float* __restrict__ b2,
           const float* __restrict__ g2,  const float* __restrict__ be2,
           const float* __restrict__ W3,  const float* __restrict__ b3,
           const float* __restrict__ g3,  const float* __restrict__ be3,
           const float* __restrict__ Wv1, const float* __restrict__ bv1,
           const float* __restrict__ gv,  const float* __restrict__ bev,
           const float* __restrict__ Wv2, const float* __restrict__ bv2,
           const float* __restrict__ Wa1, const float* __restrict__ ba1,
           const float* __restrict__ ga,  const float* __restrict__ bea,
           const float* __restrict__ Wa2, const float* __restrict__ ba2,
           const int*   __restrict__ event_type,
           float* __restrict__ out)
{
    extern __shared__ float sm[];
    float* actS  = sm + OFF_ACT;
    float* wbase = sm + OFF_W;
    float* hS    = sm + OFF_H;
    float* advS  = sm + OFF_ADV;
    float* vS    = sm + OFF_V;
    float* redS  = sm + OFF_RED;
    float* muS   = sm + OFF_MU;
    float* rsS   = sm + OFF_RS;
    int*   etS   = (int*)(sm + OFF_ET);

    int tid = threadIdx.x;
    int gr0 = blockIdx.x * TB;

    // Prologue: stage W1 tile 0 (global tile 0, buffer 0).
    stage_tile(wbase, W1, (KT * 256) >> 2, tid);
    cp_commit();

    // Load x = concat(state, time_delta) transposed into actS[k][row]
    // (overlaps with the cp.async weight prefetch above).
    for (int idx = tid; idx < TB * DIN; idx += NTHR) {
        int r = idx / DIN;
        int k = idx - r * DIN;
        float v = (k < SEQ) ? state[(size_t)(gr0 + r) * SEQ + k]
                            : time_delta[gr0 + r];
        actS[k * LDA + r] = v;
    }
    if (tid < TB) etS[tid] = event_type[gr0 + tid];
    // (gemm's leading cp_wait+__syncthreads orders these writes before compute)

    int gt = 0;

    // Trunk: 200->256->256->128, LN+ReLU each
    gemm_bias<256, false>(W1, b1, 200, actS, wbase, actS, W2, 256,
                          gt, tid, 0, 0);
    ln_relu(actS, 256, g1, be1, tid, redS, muS, rsS);
    gemm_bias<256, false>(W2, b2, 256, actS, wbase, actS, W3, 128,
                          gt, tid, 0, 0);
    ln_relu(actS, 256, g2, be2, tid, redS, muS, rsS);
    gemm_bias<128, false>(W3, b3, 256, actS, wbase, actS, Wv1, 64,
                          gt, tid, 0, 0);
    ln_relu(actS, 128, g3, be3, tid, redS, muS, rsS);

    // Value head: f(128) -> 64 -> LN+ReLU -> scalar
    gemm_bias<64, false>(Wv1, bv1, 128, actS, wbase, hS, Wa1, 64,
                         gt, tid, 0, 0);
    ln_relu(hS, 64, gv, bev, tid, redS, muS, rsS);
    if (tid < TB) {
        float a = 0.f;
        for (int k = 0; k < 64; ++k) a += hS[k * LDA + tid] * Wv2[k];
        vS[tid] = a + bv2[0];
    }

    // Advantage heads: compute all 3, commit rows matching event_type.
    // Next-tile prefetch chain threads through all remaining layers.
    gemm_bias<64, false>(Wa1, ba1, 128, actS, wbase, hS, Wa2, 32,
                         gt, tid, 0, 0);
    ln_relu(hS, 64, ga, bea, tid, redS, muS, rsS);
    gemm_bias<32, true>(Wa2, ba2, 64, hS, wbase, advS, Wa1 + 8192, 64,
                        gt, tid, etS, 0);

    gemm_bias<64, false>(Wa1 + 8192, ba1 + 64, 128, actS, wbase, hS, Wa2 + 2048, 32,
                         gt, tid, 0, 0);
    ln_relu(hS, 64, ga + 64, bea + 64, tid, redS, muS, rsS);
    gemm_bias<32, true>(Wa2 + 2048, ba2 + 32, 64, hS, wbase, advS, Wa1 + 16384, 64,
                        gt, tid, etS, 1);

    gemm_bias<64, false>(Wa1 + 16384, ba1 + 128, 128, actS, wbase, hS, Wa2 + 4096, 32,
                         gt, tid, 0, 0);
    ln_relu(hS, 64, ga + 128, bea + 128, tid, redS, muS, rsS);
    gemm_bias<32, true>(Wa2 + 4096, ba2 + 64, 64, hS, wbase, advS, (const float*)0, 0,
                        gt, tid, etS, 2);

    // out = v + adv - mean(adv)
    if (tid < TB) {
        float s = 0.f;
        #pragma unroll
        for (int c = 0; c < 32; ++c) s += advS[c * LDA + tid];
        muS[tid] = s * (1.0f / 32.0f);
    }
    __syncthreads();
    for (int idx = tid; idx < TB * 32; idx += NTHR) {
        int r = idx >> 5, c = idx & 31;
        out[(size_t)(gr0 + r) * 32 + c] = vS[r] + advS[c * LDA + r] - muS[r];
    }
}

// ---------------------------------------------------------------------------
extern "C" void kernel_launch(void* const* d_in, const int* in_sizes, int n_in,
                              void* d_out, int out_size)
{
    (void)in_sizes; (void)n_in; (void)out_size;
    cudaFuncSetAttribute(dqn_kernel,
                         cudaFuncAttributeMaxDynamicSharedMemorySize, SMEM_BYTES);

    const float* state      = (const float*)d_in[0];
    const float* time_delta = (const float*)d_in[1];
    const float* W1  = (const float*)d_in[2];
    const float* b1  = (const float*)d_in[3];
    const float* g1  = (const float*)d_in[4];
    const float* be1 = (const float*)d_in[5];
    const float* W2  = (const float*)d_in[6];
    const float* b2  = (const float*)d_in[7];
    const float* g2  = (const float*)d_in[8];
    const float* be2 = (const float*)d_in[9];
    const float* W3  = (const float*)d_in[10];
    const float* b3  = (const float*)d_in[11];
    const float* g3  = (const float*)d_in[12];
    const float* be3 = (const float*)d_in[13];
    const float* Wv1 = (const float*)d_in[14];
    const float* bv1 = (const float*)d_in[15];
    const float* gv  = (const float*)d_in[16];
    const float* bev = (const float*)d_in[17];
    const float* Wv2 = (const float*)d_in[18];
    const float* bv2 = (const float*)d_in[19];
    const float* Wa1 = (const float*)d_in[20];
    const float* ba1 = (const float*)d_in[21];
    const float* ga  = (const float*)d_in[22];
    const float* bea = (const float*)d_in[23];
    const float* Wa2 = (const float*)d_in[24];
    const float* ba2 = (const float*)d_in[25];
    const int*   et  = (const int*)d_in[26];

    dqn_kernel<<<BATCH / TB, NTHR, SMEM_BYTES>>>(
        state, time_delta, W1, b1, g1, be1, W2, b2, g2, be2,
        W3, b3, g3, be3, Wv1, bv1, gv, bev, Wv2, bv2,
        Wa1, ba1, ga, bea, Wa2, ba2, et, (float*)d_out);
}

// round 11
// speedup vs baseline: 1.1195x; 1.1195x over previous
#include <cuda_runtime.h>
#include <cstdint>

typedef unsigned long long ull;

// ---------------------------------------------------------------------------
// Packed f32x2 helpers (Blackwell sm_103a): FFMA2 only reachable via PTX.
// ---------------------------------------------------------------------------
static __device__ __forceinline__ ull ffma2(ull a, ull b, ull c) {
    ull d;
    asm("fma.rn.f32x2 %0, %1, %2, %3;" : "=l"(d) : "l"(a), "l"(b), "l"(c));
    return d;
}
static __device__ __forceinline__ ull pack2(float x) {
    ull r;
    asm("mov.b64 %0, {%1, %2};" : "=l"(r) : "f"(x), "f"(x));
    return r;
}
static __device__ __forceinline__ void unpack2(ull v, float& lo, float& hi) {
    asm("mov.b64 {%0, %1}, %2;" : "=f"(lo), "=f"(hi) : "l"(v));
}

// ---------------------------------------------------------------------------
// cp.async helpers
// ---------------------------------------------------------------------------
static __device__ __forceinline__ void cp16(uint32_t dst, const void* src) {
    asm volatile("cp.async.cg.shared.global [%0], [%1], 16;\n" :: "r"(dst), "l"(src));
}
static __device__ __forceinline__ void cp_commit() {
    asm volatile("cp.async.commit_group;\n" ::);
}
template<int W>
static __device__ __forceinline__ void cp_wait() {
    asm volatile("cp.async.wait_group %0;\n" :: "n"(W));
}

// ---------------------------------------------------------------------------
// Problem constants. TB=64 rows/CTA, 256 threads, 2 CTAs/SM (independent
// barrier domains -> one CTA computes while the other syncs/stages).
// ---------------------------------------------------------------------------
#define BATCH   131072
#define SEQ     199
#define DIN     200
#define TB      64          // batch rows per block
#define NTHR    256
#define LDA     68          // activation smem stride (mult of 4 -> LDS.128 A)
#define KT      16          // k-rows per W tile
#define WBUF    4096        // floats per W buffer (16 x 256 max tile)

// Shared memory layout (float offsets). hS / advS live in the UPPER rows of
// the activation buffer (feature rows >=128 are dead once layer 3 has run:
// all later GEMMs read only f = rows 0..127).
#define OFF_ACT   0                        // 256*68 = 17408
#define OFF_W     17408                    // 2*4096 =  8192
#define OFF_RED   25600                    // 512
#define OFF_MU    26112                    // 64
#define OFF_RS    26176                    // 64
#define OFF_V     26240                    // 64
#define OFF_ET    26304                    // 64 (int)
#define SMEM_FLOATS 26368
#define SMEM_BYTES  (SMEM_FLOATS * 4)      // 105472  (2 CTAs = 211 KB <= 227)

#define OFF_H    (128 * LDA)               // inside actS: rows 128..191
#define OFF_ADV  (192 * LDA)               // inside actS: rows 192..223

// ---------------------------------------------------------------------------
// Stage a W tile (nfloat4 float4's) into smem via cp.async (all threads).
// ---------------------------------------------------------------------------
static __device__ __forceinline__ void stage_tile(float* dst, const float* src,
                                                  int nfloat4, int tid)
{
    uint32_t d = (uint32_t)__cvta_generic_to_shared(dst);
    const float4* s = (const float4*)src;
    for (int i = tid; i < nfloat4; i += NTHR)
        cp16(d + i * 16, s + i);
}

// ---------------------------------------------------------------------------
// GEMM inner bodies (proven R8 mapping).
// NP>=2: thread owns col quads 64q+4cx (NQ=NP/2 quads -> LDS.128 W).
// NP==1: thread owns col pair 2cx (LDS.64 W).
// A: 4 contiguous rows via one LDS.128, broadcast-packed.
// ---------------------------------------------------------------------------
#define GEMM_BODY_Q(i)                                                       \
  {                                                                          \
    float4 av = *(const float4*)(ip + (i) * LDA);                            \
    ull pa0 = pack2(av.x), pa1 = pack2(av.y);                                \
    ull pa2 = pack2(av.z), pa3 = pack2(av.w);                                \
    const ulonglong2* w128 = (const ulonglong2*)(wS + (i) * N);              \
    _Pragma("unroll")                                                        \
    for (int q = 0; q < NQ; ++q) {                                           \
      ulonglong2 w = w128[16 * q + cx];                                      \
      acc[0][2*q]   = ffma2(pa0, w.x, acc[0][2*q]);                          \
      acc[0][2*q+1] = ffma2(pa0, w.y, acc[0][2*q+1]);                        \
      acc[1][2*q]   = ffma2(pa1, w.x, acc[1][2*q]);                          \
      acc[1][2*q+1] = ffma2(pa1, w.y, acc[1][2*q+1]);                        \
      acc[2][2*q]   = ffma2(pa2, w.x, acc[2][2*q]);                          \
      acc[2][2*q+1] = ffma2(pa2, w.y, acc[2][2*q+1]);                        \
      acc[3][2*q]   = ffma2(pa3, w.x, acc[3][2*q]);                          \
      acc[3][2*q+1] = ffma2(pa3, w.y, acc[3][2*q+1]);                        \
    }                                                                        \
  }

#define GEMM_BODY_P(i)                                                       \
  {                                                                          \
    float4 av = *(const float4*)(ip + (i) * LDA);                            \
    ull pa0 = pack2(av.x), pa1 = pack2(av.y);                                \
    ull pa2 = pack2(av.z), pa3 = pack2(av.w);                                \
    const ull* w64 = (const ull*)(wS + (i) * N);                             \
    ull w = w64[cx];                                                         \
    acc[0][0] = ffma2(pa0, w, acc[0][0]);                                    \
    acc[1][0] = ffma2(pa1, w, acc[1][0]);                                    \
    acc[2][0] = ffma2(pa2, w, acc[2][0]);                                    \
    acc[3][0] = ffma2(pa3, w, acc[3][0]);                                    \
  }

// ---------------------------------------------------------------------------
// C[TB x N] = A[TB x K] * W[K x N] + b. Register-accumulated (in-place safe).
// Double-buffered cp.async W pipeline, distance-1 prefetch; last iteration
// prefetches the NEXT gemm's first tile (16 x nextN). gt = global tile
// counter (buffer parity), advanced by ntiles.
// If PRED, only rows with etS[row]==esel commit.
// ---------------------------------------------------------------------------
template<int NP, bool PRED>
static __device__ __forceinline__ void gemm_bias(
    const float* __restrict__ Wg, const float* __restrict__ bg, int K,
    const float* inS, float* wbase, float* outS,
    const float* nextW, int nextN,
    int& gt, int tid, int cx, int ry, const int* etS, int esel)
{
    constexpr int N  = NP * 32;
    constexpr int NQ = (NP >= 2) ? NP / 2 : 1;
    ull acc[4][NP];
    #pragma unroll
    for (int r = 0; r < 4; ++r)
        #pragma unroll
        for (int p = 0; p < NP; ++p) acc[r][p] = 0ull;

    int ntiles = (K + KT - 1) / KT;
    for (int t = 0; t < ntiles; ++t) {
        cp_wait<0>();          // tile t resident
        __syncthreads();       // ...visible to all; compute t-1 fully done
        int g = t + 1;         // issue tile t+1 (own layer or next layer)
        float* dstb = wbase + ((gt + g) & 1) * WBUF;
        if (g < ntiles) {
            int rows = min(KT, K - g * KT);
            stage_tile(dstb, Wg + (size_t)g * KT * N, (rows * N) >> 2, tid);
            cp_commit();
        } else if (nextW) {
            stage_tile(dstb, nextW, (KT * nextN) >> 2, tid);
            cp_commit();
        }

        int ks = min(KT, K - t * KT);
        const float* wS = wbase + ((gt + t) & 1) * WBUF;
        const float* ip = inS + t * KT * LDA + ry * 4;
        if constexpr (NP >= 2) {
            if (ks == KT) {
                #pragma unroll
                for (int i = 0; i < KT; ++i) GEMM_BODY_Q(i)
            } else {
                for (int i = 0; i < ks; ++i) GEMM_BODY_Q(i)
            }
        } else {
            if (ks == KT) {
                #pragma unroll
                for (int i = 0; i < KT; ++i) GEMM_BODY_P(i)
            } else {
                for (int i = 0; i < ks; ++i) GEMM_BODY_P(i)
            }
        }
    }
    gt += ntiles;

    __syncthreads();   // all reads of inS done -> safe to overwrite (in-place)
    #pragma unroll
    for (int r = 0; r < 4; ++r) {
        int row = ry * 4 + r;
        if (!PRED || etS[row] == esel) {
            if constexpr (NP >= 2) {
                #pragma unroll
                for (int q = 0; q < NQ; ++q) {
                    int c0 = 64 * q + 4 * cx;
                    float v0, v1, v2, v3;
                    unpack2(acc[r][2*q],   v0, v1);
                    unpack2(acc[r][2*q+1], v2, v3);
                    outS[(c0 + 0) * LDA + row] = v0 + bg[c0 + 0];
                    outS[(c0 + 1) * LDA + row] = v1 + bg[c0 + 1];
                    outS[(c0 + 2) * LDA + row] = v2 + bg[c0 + 2];
                    outS[(c0 + 3) * LDA + row] = v3 + bg[c0 + 3];
                }
            } else {
                int c0 = 2 * cx;
                float lo, hi; unpack2(acc[r][0], lo, hi);
                outS[(c0 + 0) * LDA + row] = lo + bg[c0 + 0];
                outS[(c0 + 1) * LDA + row] = hi + bg[c0 + 1];
            }
        }
    }
    __syncthreads();
}

// ---------------------------------------------------------------------------
// In-place LayerNorm(+affine)+ReLU over feature dim N for TB=64 rows.
// 4 partial threads per row.
// ---------------------------------------------------------------------------
static __device__ __forceinline__ void ln_relu(
    float* S, int N, const float* __restrict__ g, const float* __restrict__ be,
    int tid, float* redS, float* muS, float* rsS)
{
    int row = tid & 63;
    int p   = tid >> 6;
    int seg = N >> 2;
    float s = 0.f, sq = 0.f;
    for (int i = 0; i < seg; ++i) {
        float v = S[(p * seg + i) * LDA + row];
        s += v; sq += v * v;
    }
    redS[p * 64 + row]       = s;
    redS[256 + p * 64 + row] = sq;
    __syncthreads();
    if (tid < 64) {
        float ts = 0.f, tq = 0.f;
        #pragma unroll
        for (int pp = 0; pp < 4; ++pp) {
            ts += redS[pp * 64 + tid];
            tq += redS[256 + pp * 64 + tid];
        }
        float mu  = ts / (float)N;
        float var = tq / (float)N - mu * mu;
        muS[tid] = mu;
        rsS[tid] = rsqrtf(var + 1e-5f);
    }
    __syncthreads();
    float mu = muS[row], rs = rsS[row];
    for (int i = 0; i < seg; ++i) {
        int col = p * seg + i;
        float v = S[col * LDA + row];
        v = (v - mu) * rs * g[col] + be[col];
        S[col * LDA + row] = fmaxf(v, 0.f);
    }
    __syncthreads();
}

// ---------------------------------------------------------------------------
// Fused dueling-DQN forward. One block = 64 batch rows; 2 blocks/SM.
// ---------------------------------------------------------------------------
__global__ void __launch_bounds__(NTHR, 2)
dqn_kernel(const float* __restrict__ state, const float* __restrict__ time_delta,
           const float* __restrict__ W1,  const float* __restrict__ b1,
           const float* __restrict__ g1,  const float* __restrict__ be1,
           const float* __restrict__ W2,  const float* __restrict__ b2,
           const float* __restrict__ g2,  const float* __restrict__ be2,
           const float* __restrict__ W3,  const float* __restrict__ b3,
           const float* __restrict__ g3,  const float* __restrict__ be3,
           const float* __restrict__ Wv1, const float* __restrict__ bv1,
           const float* __restrict__ gv,  const float* __restrict__ bev,
           const float* __restrict__ Wv2, const float* __restrict__ bv2,
           const float* __restrict__ Wa1, const float* __restrict__ ba1,
           const float* __restrict__ ga,  const float* __restrict__ bea,
           const float* __restrict__ Wa2, const float* __restrict__ ba2,
           const int*   __restrict__ event_type,
           float* __restrict__ out)
{
    extern __shared__ float sm[];
    float* actS  = sm + OFF_ACT;
    float* wbase = sm + OFF_W;
    float* hS    = actS + OFF_H;     // rows 128..191 of act buffer
    float* advS  = actS + OFF_ADV;   // rows 192..223 of act buffer
    float* redS  = sm + OFF_RED;
    float* muS   = sm + OFF_MU;
    float* rsS   = sm + OFF_RS;
    float* vS    = sm + OFF_V;
    int*   etS   = (int*)(sm + OFF_ET);

    int tid = threadIdx.x;
    int cx  = tid & 15;
    int ry  = tid >> 4;
    int gr0 = blockIdx.x * TB;

    // Prologue: stage W1 tile 0 (global tile 0, buffer 0).
    stage_tile(wbase, W1, (KT * 256) >> 2, tid);
    cp_commit();

    // Load x = concat(state, time_delta) transposed into actS[k][row]
    // (overlaps with the cp.async weight prefetch above).
    for (int idx = tid; idx < TB * DIN; idx += NTHR) {
        int r = idx / DIN;
        int k = idx - r * DIN;
        float v = (k < SEQ) ? state[(size_t)(gr0 + r) * SEQ + k]
                            : time_delta[gr0 + r];
        actS[k * LDA + r] = v;
    }
    if (tid < TB) etS[tid] = event_type[gr0 + tid];
    // (gemm's leading cp_wait+__syncthreads orders these writes before compute)

    int gt = 0;

    // Trunk: 200->256->256->128, LN+ReLU each
    gemm_bias<8, false>(W1, b1, 200, actS, wbase, actS, W2, 256,
                        gt, tid, cx, ry, 0, 0);
    ln_relu(actS, 256, g1, be1, tid, redS, muS, rsS);
    gemm_bias<8, false>(W2, b2, 256, actS, wbase, actS, W3, 128,
                        gt, tid, cx, ry, 0, 0);
    ln_relu(actS, 256, g2, be2, tid, redS, muS, rsS);
    gemm_bias<4, false>(W3, b3, 256, actS, wbase, actS, Wv1, 64,
                        gt, tid, cx, ry, 0, 0);
    ln_relu(actS, 128, g3, be3, tid, redS, muS, rsS);

    // Value head: f(128) -> 64 -> LN+ReLU -> scalar.
    // hS sits in act rows 128..191 (dead above f=128 features).
    gemm_bias<2, false>(Wv1, bv1, 128, actS, wbase, hS, Wa1, 64,
                        gt, tid, cx, ry, 0, 0);
    ln_relu(hS, 64, gv, bev, tid, redS, muS, rsS);
    if (tid < TB) {
        float a = 0.f;
        for (int k = 0; k < 64; ++k) a += hS[k * LDA + tid] * Wv2[k];
        vS[tid] = a + bv2[0];
    }

    // Advantage heads: compute all 3, commit rows matching event_type.
    // Next-tile prefetch chain threads through all remaining layers.
    gemm_bias<2, false>(Wa1, ba1, 128, actS, wbase, hS, Wa2, 32,
                        gt, tid, cx, ry, 0, 0);
    ln_relu(hS, 64, ga, bea, tid, redS, muS, rsS);
    gemm_bias<1, true>(Wa2, ba2, 64, hS, wbase, advS, Wa1 + 8192, 64,
                       gt, tid, cx, ry, etS, 0);

    gemm_bias<2, false>(Wa1 + 8192, ba1 + 64, 128, actS, wbase, hS, Wa2 + 2048, 32,
                        gt, tid, cx, ry, 0, 0);
    ln_relu(hS, 64, ga + 64, bea + 64, tid, redS, muS, rsS);
    gemm_bias<1, true>(Wa2 + 2048, ba2 + 32, 64, hS, wbase, advS, Wa1 + 16384, 64,
                       gt, tid, cx, ry, etS, 1);

    gemm_bias<2, false>(Wa1 + 16384, ba1 + 128, 128, actS, wbase, hS, Wa2 + 4096, 32,
                        gt, tid, cx, ry, 0, 0);
    ln_relu(hS, 64, ga + 128, bea + 128, tid, redS, muS, rsS);
    gemm_bias<1, true>(Wa2 + 4096, ba2 + 64, 64, hS, wbase, advS, (const float*)0, 0,
                       gt, tid, cx, ry, etS, 2);

    // out = v + adv - mean(adv)
    if (tid < TB) {
        float s = 0.f;
        #pragma unroll
        for (int c = 0; c < 32; ++c) s += advS[c * LDA + tid];
        muS[tid] = s * (1.0f / 32.0f);
    }
    __syncthreads();
    for (int idx = tid; idx < TB * 32; idx += NTHR) {
        int r = idx >> 5, c = idx & 31;
        out[(size_t)(gr0 + r) * 32 + c] = vS[r] + advS[c * LDA + r] - muS[r];
    }
}

// ---------------------------------------------------------------------------
extern "C" void kernel_launch(void* const* d_in, const int* in_sizes, int n_in,
                              void* d_out, int out_size)
{
    (void)in_sizes; (void)n_in; (void)out_size;
    cudaFuncSetAttribute(dqn_kernel,
                         cudaFuncAttributeMaxDynamicSharedMemorySize, SMEM_BYTES);

    const float* state      = (const float*)d_in[0];
    const float* time_delta = (const float*)d_in[1];
    const float* W1  = (const float*)d_in[2];
    const float* b1  = (const float*)d_in[3];
    const float* g1  = (const float*)d_in[4];
    const float* be1 = (const float*)d_in[5];
    const float* W2  = (const float*)d_in[6];
    const float* b2  = (const float*)d_in[7];
    const float* g2  = (const float*)d_in[8];
    const float* be2 = (const float*)d_in[9];
    const float* W3  = (const float*)d_in[10];
    const float* b3  = (const float*)d_in[11];
    const float* g3  = (const float*)d_in[12];
    const float* be3 = (const float*)d_in[13];
    const float* Wv1 = (const float*)d_in[14];
    const float* bv1 = (const float*)d_in[15];
    const float* gv  = (const float*)d_in[16];
    const float* bev = (const float*)d_in[17];
    const float* Wv2 = (const float*)d_in[18];
    const float* bv2 = (const float*)d_in[19];
    const float* Wa1 = (const float*)d_in[20];
    const float* ba1 = (const float*)d_in[21];
    const float* ga  = (const float*)d_in[22];
    const float* bea = (const float*)d_in[23];
    const float* Wa2 = (const float*)d_in[24];
    const float* ba2 = (const float*)d_in[25];
    const int*   et  = (const int*)d_in[26];

    dqn_kernel<<<BATCH / TB, NTHR, SMEM_BYTES>>>(
        state, time_delta, W1, b1, g1, be1, W2, b2, g2, be2,
        W3, b3, g3, be3, Wv1, bv1, gv, bev, Wv2, bv2,
        Wa1, ba1, ga, bea, Wa2, ba2, et, (float*)d_out);
}